// round 1
// baseline (speedup 1.0000x reference)
#include <cuda_runtime.h>
#include <cuda_bf16.h>
#include <cstdint>

// Problem constants (fixed shapes for this problem instance)
#define MAXN 50000
#define MAXE 800000
#define D    128

// Static device scratch (no allocation allowed)
__device__ float g_denom[MAXN];
__device__ float g_deg[MAXN];
__device__ float g_agg1[MAXN * D];
__device__ float g_agg2[MAXN * D];
__device__ float g_h[MAXN * D];

// ---------------------------------------------------------------------------
// Zero scratch
// ---------------------------------------------------------------------------
__global__ void zero_kernel(int n_nodes) {
    int i = blockIdx.x * blockDim.x + threadIdx.x;
    int total = n_nodes * D;
    if (i < total) {
        g_agg1[i] = 0.0f;
        g_agg2[i] = 0.0f;
    }
    if (i < n_nodes) {
        g_denom[i] = 0.0f;
        g_deg[i]   = 0.0f;
    }
}

// ---------------------------------------------------------------------------
// Edge pass 1: denom (sum of w into dst) and degree (count into dst).
// Shared by both layers (w/src/dst identical).
// ---------------------------------------------------------------------------
__global__ void edge_deg_kernel(const float* __restrict__ w,
                                const int* __restrict__ dst,
                                int n_edges) {
    int e = blockIdx.x * blockDim.x + threadIdx.x;
    if (e >= n_edges) return;
    int d = dst[e];
    atomicAdd(&g_denom[d], w[e]);
    atomicAdd(&g_deg[d], 1.0f);
}

// ---------------------------------------------------------------------------
// Edge aggregation: warp per edge.
// agg[dst] += x[src] * (w / max(denom[dst], 1e-12))
// Each lane handles 4 consecutive floats (float4), scatter via red.v4 (no return).
// ---------------------------------------------------------------------------
__device__ __forceinline__ void red_add_v4(float* p, float4 v) {
    asm volatile("red.global.add.v4.f32 [%0], {%1,%2,%3,%4};"
                 :: "l"(p), "f"(v.x), "f"(v.y), "f"(v.z), "f"(v.w)
                 : "memory");
}

__global__ void __launch_bounds__(256) edge_agg_kernel(
    const float* __restrict__ x,
    const float* __restrict__ w,
    const int* __restrict__ src,
    const int* __restrict__ dst,
    float* __restrict__ agg,
    int n_edges)
{
    int gtid = blockIdx.x * blockDim.x + threadIdx.x;
    int e = gtid >> 5;
    int lane = gtid & 31;
    if (e >= n_edges) return;

    int s = src[e];
    int d = dst[e];
    float nw = w[e] / fmaxf(g_denom[d], 1e-12f);

    const float4* xp = reinterpret_cast<const float4*>(x + (size_t)s * D) + lane;
    float4 v = *xp;
    v.x *= nw; v.y *= nw; v.z *= nw; v.w *= nw;

    float* ap = agg + (size_t)d * D + lane * 4;
    red_add_v4(ap, v);
}

// ---------------------------------------------------------------------------
// Fused node MLP: out = relu((x + agg / max(deg,1)) @ W^T + b)
// W is [DOUT, 128] row-major. Tiled GEMM, BM=64 rows, full DOUT width, BK=32.
// 256 threads; thread computes TM rows x 8 cols.
//   DOUT=128: NCG=16 col-groups, 16 row-groups, TM=4
//   DOUT=64:  NCG=8  col-groups, 32 row-groups, TM=2
// ---------------------------------------------------------------------------
template <int DOUT, int TM>
__global__ void __launch_bounds__(256) gin_mlp_kernel(
    const float* __restrict__ xin,
    const float* __restrict__ agg,
    const float* __restrict__ W,     // [DOUT, D]
    const float* __restrict__ bias,  // [DOUT]
    float* __restrict__ out,         // [N, DOUT]
    int N)
{
    constexpr int BM  = 64;
    constexpr int BK  = 32;
    constexpr int NCG = DOUT / 8;    // col groups of 8
    constexpr int SA  = BK + 1;      // padded A stride (33)
    constexpr int DP  = DOUT + 4;    // padded W stride (multiple of 4)

    __shared__ float sA[BM * SA];
    __shared__ float sW[BK * DP];

    const int tid = threadIdx.x;
    const int tx  = tid % NCG;       // col group
    const int ty  = tid / NCG;       // row group
    const int row0 = blockIdx.x * BM;

    float acc[TM][8];
#pragma unroll
    for (int i = 0; i < TM; i++)
#pragma unroll
        for (int j = 0; j < 8; j++) acc[i][j] = 0.0f;

    for (int kt = 0; kt < D; kt += BK) {
        // Load A tile: compute in = x + agg * invdeg on the fly.
        // BM*BK = 2048 floats = 512 float4; 2 per thread.
#pragma unroll
        for (int i = 0; i < 2; i++) {
            int idx = tid + i * 256;       // 0..511
            int r   = idx >> 3;            // row within tile (8 float4 per row)
            int c4  = idx & 7;
            int grow = row0 + r;
            float4 v = make_float4(0.f, 0.f, 0.f, 0.f);
            if (grow < N) {
                int gcol = kt + c4 * 4;
                float id = 1.0f / fmaxf(g_deg[grow], 1.0f);
                float4 xv = *reinterpret_cast<const float4*>(xin + (size_t)grow * D + gcol);
                float4 av = *reinterpret_cast<const float4*>(agg + (size_t)grow * D + gcol);
                v.x = fmaf(av.x, id, xv.x);
                v.y = fmaf(av.y, id, xv.y);
                v.z = fmaf(av.z, id, xv.z);
                v.w = fmaf(av.w, id, xv.w);
            }
            float* sa = sA + r * SA + c4 * 4;
            sa[0] = v.x; sa[1] = v.y; sa[2] = v.z; sa[3] = v.w;
        }
        // Load W tile transposed: sW[kk][j] = W[j][kt+kk]
        for (int idx = tid; idx < DOUT * BK; idx += 256) {
            int j  = idx / BK;
            int kk = idx % BK;
            sW[kk * DP + j] = W[j * D + kt + kk];
        }
        __syncthreads();

#pragma unroll
        for (int kk = 0; kk < BK; kk++) {
            float a[TM];
#pragma unroll
            for (int i = 0; i < TM; i++)
                a[i] = sA[(ty * TM + i) * SA + kk];
            float4 b0 = *reinterpret_cast<const float4*>(sW + kk * DP + tx * 8);
            float4 b1 = *reinterpret_cast<const float4*>(sW + kk * DP + tx * 8 + 4);
            float b[8] = {b0.x, b0.y, b0.z, b0.w, b1.x, b1.y, b1.z, b1.w};
#pragma unroll
            for (int i = 0; i < TM; i++)
#pragma unroll
                for (int j = 0; j < 8; j++)
                    acc[i][j] = fmaf(a[i], b[j], acc[i][j]);
        }
        __syncthreads();
    }

    // Epilogue: bias + relu
    float bi[8];
#pragma unroll
    for (int j = 0; j < 8; j++) bi[j] = bias[tx * 8 + j];

#pragma unroll
    for (int i = 0; i < TM; i++) {
        int grow = row0 + ty * TM + i;
        if (grow < N) {
            float* op = out + (size_t)grow * DOUT + tx * 8;
            float4 o0, o1;
            o0.x = fmaxf(acc[i][0] + bi[0], 0.f);
            o0.y = fmaxf(acc[i][1] + bi[1], 0.f);
            o0.z = fmaxf(acc[i][2] + bi[2], 0.f);
            o0.w = fmaxf(acc[i][3] + bi[3], 0.f);
            o1.x = fmaxf(acc[i][4] + bi[4], 0.f);
            o1.y = fmaxf(acc[i][5] + bi[5], 0.f);
            o1.z = fmaxf(acc[i][6] + bi[6], 0.f);
            o1.w = fmaxf(acc[i][7] + bi[7], 0.f);
            *reinterpret_cast<float4*>(op)     = o0;
            *reinterpret_cast<float4*>(op + 4) = o1;
        }
    }
}

// ---------------------------------------------------------------------------
// Launch
// ---------------------------------------------------------------------------
extern "C" void kernel_launch(void* const* d_in, const int* in_sizes, int n_in,
                              void* d_out, int out_size) {
    const float* x  = (const float*)d_in[0];
    const float* w  = (const float*)d_in[1];
    const float* W1 = (const float*)d_in[2];
    const float* b1 = (const float*)d_in[3];
    const float* W2 = (const float*)d_in[4];
    const float* b2 = (const float*)d_in[5];
    const int*   src = (const int*)d_in[6];
    const int*   dst = (const int*)d_in[7];
    float* out = (float*)d_out;

    const int N = in_sizes[0] / D;   // 50000
    const int E = in_sizes[1];       // 800000

    float* agg1;  cudaGetSymbolAddress((void**)&agg1,  g_agg1);
    float* agg2;  cudaGetSymbolAddress((void**)&agg2,  g_agg2);
    float* h;     cudaGetSymbolAddress((void**)&h,     g_h);

    // 1. Zero scratch
    {
        int total = N * D;
        zero_kernel<<<(total + 255) / 256, 256>>>(N);
    }
    // 2. denom + deg (shared by both layers)
    edge_deg_kernel<<<(E + 255) / 256, 256>>>(w, dst, E);

    // 3. Layer 1 aggregation
    {
        long long threads = (long long)E * 32;
        int blocks = (int)((threads + 255) / 256);
        edge_agg_kernel<<<blocks, 256>>>(x, w, src, dst, agg1, E);
    }
    // 4. Layer 1 MLP -> h
    gin_mlp_kernel<128, 4><<<(N + 63) / 64, 256>>>(x, agg1, W1, b1, h, N);

    // 5. Layer 2 aggregation (input h)
    {
        long long threads = (long long)E * 32;
        int blocks = (int)((threads + 255) / 256);
        edge_agg_kernel<<<blocks, 256>>>(h, w, src, dst, agg2, E);
    }
    // 6. Layer 2 MLP -> out
    gin_mlp_kernel<64, 2><<<(N + 63) / 64, 256>>>(h, agg2, W2, b2, out, N);
}

// round 6
// speedup vs baseline: 1.4125x; 1.4125x over previous
#include <cuda_runtime.h>
#include <cuda_bf16.h>
#include <cstdint>

#define MAXN 50000
#define MAXE 800000
#define D    128

// ---------------------------------------------------------------------------
// Static device scratch (no allocation allowed)
// ---------------------------------------------------------------------------
__device__ float g_denom[MAXN];        // sum of w into dst
__device__ int   g_deg[MAXN];          // in-degree
__device__ int   g_rowptr[MAXN + 1];   // CSR row pointers (by dst)
__device__ int   g_cursor[MAXN];       // scatter cursors
__device__ int   g_col[MAXE];          // CSR: src node per edge
__device__ float g_val[MAXE];          // CSR: w/denom/deg folded coefficient
__device__ float g_t[MAXN * D];        // combined input (x + agg) per layer
__device__ float g_h[MAXN * D];        // layer-1 output

// ---------------------------------------------------------------------------
// 1. Zero denom/deg
// ---------------------------------------------------------------------------
__global__ void zero_kernel(int n_nodes) {
    int i = blockIdx.x * blockDim.x + threadIdx.x;
    if (i < n_nodes) {
        g_denom[i] = 0.0f;
        g_deg[i]   = 0;
    }
}

// ---------------------------------------------------------------------------
// 2. Histogram: denom[dst] += w, deg[dst] += 1
// ---------------------------------------------------------------------------
__global__ void hist_kernel(const float* __restrict__ w,
                            const int* __restrict__ dst,
                            int n_edges) {
    int e = blockIdx.x * blockDim.x + threadIdx.x;
    if (e >= n_edges) return;
    int d = dst[e];
    atomicAdd(&g_denom[d], w[e]);
    atomicAdd(&g_deg[d], 1);
}

// ---------------------------------------------------------------------------
// 3. Exclusive scan of deg -> rowptr, cursor. Single block, 1024 threads.
// ---------------------------------------------------------------------------
__global__ void __launch_bounds__(1024) scan_kernel(int n_nodes, int n_edges) {
    __shared__ int sh[1024];
    const int tid = threadIdx.x;
    const int CH = (n_nodes + 1023) / 1024;
    const int base = tid * CH;

    int s = 0;
    for (int i = 0; i < CH; i++) {
        int idx = base + i;
        if (idx < n_nodes) s += g_deg[idx];
    }
    sh[tid] = s;
    __syncthreads();

    // Hillis-Steele inclusive scan
    for (int off = 1; off < 1024; off <<= 1) {
        int t = (tid >= off) ? sh[tid - off] : 0;
        __syncthreads();
        sh[tid] += t;
        __syncthreads();
    }

    int run = sh[tid] - s;   // exclusive offset for this thread's chunk
    for (int i = 0; i < CH; i++) {
        int idx = base + i;
        if (idx < n_nodes) {
            g_rowptr[idx] = run;
            g_cursor[idx] = run;
            run += g_deg[idx];
        }
    }
    if (tid == 0) g_rowptr[n_nodes] = n_edges;
}

// ---------------------------------------------------------------------------
// 4. Scatter edges into CSR, folding the full coefficient:
//    val = w / max(denom,1e-12) / max(deg,1)
// ---------------------------------------------------------------------------
__global__ void scatter_kernel(const float* __restrict__ w,
                               const int* __restrict__ src,
                               const int* __restrict__ dst,
                               int n_edges) {
    int e = blockIdx.x * blockDim.x + threadIdx.x;
    if (e >= n_edges) return;
    int d = dst[e];
    int p = atomicAdd(&g_cursor[d], 1);
    float c = w[e] / fmaxf(g_denom[d], 1e-12f) / fmaxf((float)g_deg[d], 1.0f);
    g_col[p] = src[e];
    g_val[p] = c;
}

// ---------------------------------------------------------------------------
// 5. Aggregation: warp per node, no atomics.
//    tout[v] = xin[v] + sum_{e into v} xin[col[e]] * val[e]
//    Lane handles one float4 (32 lanes * 4 = 128 features).
//    Edge loop unrolled x4 with front-batched gathers for MLP.
// ---------------------------------------------------------------------------
__global__ void __launch_bounds__(256) agg_kernel(
    const float* __restrict__ xin,
    float* __restrict__ tout,
    int n_nodes)
{
    int gtid = blockIdx.x * blockDim.x + threadIdx.x;
    int v = gtid >> 5;
    int lane = gtid & 31;
    if (v >= n_nodes) return;

    int beg = g_rowptr[v];
    int end = g_rowptr[v + 1];

    float4 acc = make_float4(0.f, 0.f, 0.f, 0.f);
    int i = beg;
    for (; i + 3 < end; i += 4) {
        int   s0 = __ldg(&g_col[i]);
        int   s1 = __ldg(&g_col[i + 1]);
        int   s2 = __ldg(&g_col[i + 2]);
        int   s3 = __ldg(&g_col[i + 3]);
        float c0 = __ldg(&g_val[i]);
        float c1 = __ldg(&g_val[i + 1]);
        float c2 = __ldg(&g_val[i + 2]);
        float c3 = __ldg(&g_val[i + 3]);
        float4 x0 = __ldg(reinterpret_cast<const float4*>(xin + (size_t)s0 * D) + lane);
        float4 x1 = __ldg(reinterpret_cast<const float4*>(xin + (size_t)s1 * D) + lane);
        float4 x2 = __ldg(reinterpret_cast<const float4*>(xin + (size_t)s2 * D) + lane);
        float4 x3 = __ldg(reinterpret_cast<const float4*>(xin + (size_t)s3 * D) + lane);
        acc.x = fmaf(x0.x, c0, acc.x); acc.y = fmaf(x0.y, c0, acc.y);
        acc.z = fmaf(x0.z, c0, acc.z); acc.w = fmaf(x0.w, c0, acc.w);
        acc.x = fmaf(x1.x, c1, acc.x); acc.y = fmaf(x1.y, c1, acc.y);
        acc.z = fmaf(x1.z, c1, acc.z); acc.w = fmaf(x1.w, c1, acc.w);
        acc.x = fmaf(x2.x, c2, acc.x); acc.y = fmaf(x2.y, c2, acc.y);
        acc.z = fmaf(x2.z, c2, acc.z); acc.w = fmaf(x2.w, c2, acc.w);
        acc.x = fmaf(x3.x, c3, acc.x); acc.y = fmaf(x3.y, c3, acc.y);
        acc.z = fmaf(x3.z, c3, acc.z); acc.w = fmaf(x3.w, c3, acc.w);
    }
    for (; i < end; i++) {
        int   s0 = __ldg(&g_col[i]);
        float c0 = __ldg(&g_val[i]);
        float4 x0 = __ldg(reinterpret_cast<const float4*>(xin + (size_t)s0 * D) + lane);
        acc.x = fmaf(x0.x, c0, acc.x); acc.y = fmaf(x0.y, c0, acc.y);
        acc.z = fmaf(x0.z, c0, acc.z); acc.w = fmaf(x0.w, c0, acc.w);
    }

    float4 xv = *(reinterpret_cast<const float4*>(xin + (size_t)v * D) + lane);
    acc.x += xv.x; acc.y += xv.y; acc.z += xv.z; acc.w += xv.w;
    *(reinterpret_cast<float4*>(tout + (size_t)v * D) + lane) = acc;
}

// ---------------------------------------------------------------------------
// 6. MLP: out = relu(t @ W^T + b).  W is [DOUT,128] row-major.
//    BM=128 rows, full DOUT cols, BK=32.  256 threads.
//    DOUT=128: 16x16 thread grid, each 8x8.  DOUT=64: 8x32 grid, each 4x8.
//    A tile stored transposed so the inner loop is pure LDS.128 + FFMA.
// ---------------------------------------------------------------------------
template <int DOUT, int TM>
__global__ void __launch_bounds__(256) mlp_kernel(
    const float* __restrict__ t,
    const float* __restrict__ W,
    const float* __restrict__ bias,
    float* __restrict__ out,
    int N)
{
    constexpr int BM  = 128;
    constexpr int BK  = 32;
    constexpr int NCG = DOUT / 8;
    constexpr int SAP = BM + 4;
    constexpr int SWP = DOUT + 4;

    __shared__ float sAT[BK][SAP];  // [k][row]
    __shared__ float sW [BK][SWP];  // [k][col]

    const int tid = threadIdx.x;
    const int tx = tid % NCG;
    const int ty = tid / NCG;
    const int row0 = blockIdx.x * BM;

    float acc[TM][8];
#pragma unroll
    for (int i = 0; i < TM; i++)
#pragma unroll
        for (int j = 0; j < 8; j++) acc[i][j] = 0.0f;

    for (int kt = 0; kt < D; kt += BK) {
        // Load A tile transposed: 128 rows x 32 cols = 1024 float4, 4/thread
#pragma unroll
        for (int i = 0; i < 4; i++) {
            int idx = tid + i * 256;
            int r = idx >> 3;
            int c4 = idx & 7;
            int grow = row0 + r;
            float4 v = make_float4(0.f, 0.f, 0.f, 0.f);
            if (grow < N)
                v = *reinterpret_cast<const float4*>(t + (size_t)grow * D + kt + c4 * 4);
            sAT[c4 * 4 + 0][r] = v.x;
            sAT[c4 * 4 + 1][r] = v.y;
            sAT[c4 * 4 + 2][r] = v.z;
            sAT[c4 * 4 + 3][r] = v.w;
        }
        // Load W tile transposed: sW[kk][j] = W[j][kt+kk]
#pragma unroll
        for (int i = 0; i < DOUT * BK / 256; i++) {
            int idx = tid + i * 256;
            int j  = idx >> 5;
            int kk = idx & 31;
            sW[kk][j] = W[j * D + kt + kk];
        }
        __syncthreads();

#pragma unroll
        for (int kk = 0; kk < BK; kk++) {
            float a[TM];
#pragma unroll
            for (int i = 0; i < TM; i += 4) {
                float4 av = *reinterpret_cast<const float4*>(&sAT[kk][ty * TM + i]);
                a[i + 0] = av.x; a[i + 1] = av.y; a[i + 2] = av.z; a[i + 3] = av.w;
            }
            float4 b0 = *reinterpret_cast<const float4*>(&sW[kk][tx * 8]);
            float4 b1 = *reinterpret_cast<const float4*>(&sW[kk][tx * 8 + 4]);
            float b[8] = {b0.x, b0.y, b0.z, b0.w, b1.x, b1.y, b1.z, b1.w};
#pragma unroll
            for (int i = 0; i < TM; i++)
#pragma unroll
                for (int j = 0; j < 8; j++)
                    acc[i][j] = fmaf(a[i], b[j], acc[i][j]);
        }
        __syncthreads();
    }

    float bi[8];
#pragma unroll
    for (int j = 0; j < 8; j++) bi[j] = bias[tx * 8 + j];

#pragma unroll
    for (int i = 0; i < TM; i++) {
        int grow = row0 + ty * TM + i;
        if (grow < N) {
            float* op = out + (size_t)grow * DOUT + tx * 8;
            float4 o0, o1;
            o0.x = fmaxf(acc[i][0] + bi[0], 0.f);
            o0.y = fmaxf(acc[i][1] + bi[1], 0.f);
            o0.z = fmaxf(acc[i][2] + bi[2], 0.f);
            o0.w = fmaxf(acc[i][3] + bi[3], 0.f);
            o1.x = fmaxf(acc[i][4] + bi[4], 0.f);
            o1.y = fmaxf(acc[i][5] + bi[5], 0.f);
            o1.z = fmaxf(acc[i][6] + bi[6], 0.f);
            o1.w = fmaxf(acc[i][7] + bi[7], 0.f);
            *reinterpret_cast<float4*>(op)     = o0;
            *reinterpret_cast<float4*>(op + 4) = o1;
        }
    }
}

// ---------------------------------------------------------------------------
// Launch
// ---------------------------------------------------------------------------
extern "C" void kernel_launch(void* const* d_in, const int* in_sizes, int n_in,
                              void* d_out, int out_size) {
    const float* x   = (const float*)d_in[0];
    const float* w   = (const float*)d_in[1];
    const float* W1  = (const float*)d_in[2];
    const float* b1  = (const float*)d_in[3];
    const float* W2  = (const float*)d_in[4];
    const float* b2  = (const float*)d_in[5];
    const int*   src = (const int*)d_in[6];
    const int*   dst = (const int*)d_in[7];
    float* out = (float*)d_out;

    const int N = in_sizes[0] / D;   // 50000
    const int E = in_sizes[1];       // 800000

    float* t;  cudaGetSymbolAddress((void**)&t, g_t);
    float* h;  cudaGetSymbolAddress((void**)&h, g_h);

    // CSR build (shared by both layers)
    zero_kernel<<<(N + 255) / 256, 256>>>(N);
    hist_kernel<<<(E + 255) / 256, 256>>>(w, dst, E);
    scan_kernel<<<1, 1024>>>(N, E);
    scatter_kernel<<<(E + 255) / 256, 256>>>(w, src, dst, E);

    const int aggBlocks = (N * 32 + 255) / 256;

    // Layer 1
    agg_kernel<<<aggBlocks, 256>>>(x, t, N);
    mlp_kernel<128, 8><<<(N + 127) / 128, 256>>>(t, W1, b1, h, N);

    // Layer 2
    agg_kernel<<<aggBlocks, 256>>>(h, t, N);
    mlp_kernel<64, 4><<<(N + 127) / 128, 256>>>(t, W2, b2, out, N);
}